// round 6
// baseline (speedup 1.0000x reference)
#include <cuda_runtime.h>
#include <math.h>
#include <stdint.h>

#define DEV_INLINE __device__ __forceinline__

// Problem dims
constexpr int Bc = 2;
constexpr int Lc = 2048;
constexpr int Dc = 1024;
constexpr int Hc = 16;
constexpr int HDc = 64;
constexpr int Mc = Bc * Lc;      // 4096 rows
constexpr int DFc = 4096;        // FFN hidden

// -------- scratch (static device globals; no allocation at runtime) --------
__device__ float g_xn [Mc * Dc];
__device__ float g_yq [Mc * Dc];
__device__ float g_yk [Mc * Dc];
__device__ float g_yv [Mc * Dc];
__device__ float g_q  [Mc * Dc];
__device__ float g_k  [Mc * Dc];
__device__ float g_v  [Mc * Dc];
__device__ float g_k2 [Bc * Hc * Lc];
__device__ float g_att[Mc * Dc];
__device__ float g_o  [Mc * Dc];
__device__ float g_x2 [Mc * Dc];
__device__ float g_ffh[(size_t)Mc * DFc];
__device__ float g_f2 [Mc * Dc];
// tf32-rounded weights
__device__ float g_twq[Dc * Dc];
__device__ float g_twk[Dc * Dc];
__device__ float g_twv[Dc * Dc];
__device__ float g_two[Dc * Dc];
__device__ float g_tw1[(size_t)DFc * Dc];
__device__ float g_tw2[(size_t)Dc * DFc];

DEV_INLINE float warp_sum(float v) {
    #pragma unroll
    for (int o = 16; o > 0; o >>= 1) v += __shfl_xor_sync(0xffffffffu, v, o);
    return v;
}

DEV_INLINE uint32_t f2tf(float x) {
    uint32_t r;
    asm("cvt.rna.tf32.f32 %0, %1;" : "=r"(r) : "f"(x));
    return r;
}
DEV_INLINE float f2tf_f(float x) { return __uint_as_float(f2tf(x)); }

DEV_INLINE void mma_tf32(float* c, const uint32_t* a, const uint32_t* b) {
    asm volatile(
        "mma.sync.aligned.m16n8k8.row.col.f32.tf32.tf32.f32 "
        "{%0,%1,%2,%3}, {%4,%5,%6,%7}, {%8,%9}, {%0,%1,%2,%3};\n"
        : "+f"(c[0]), "+f"(c[1]), "+f"(c[2]), "+f"(c[3])
        : "r"(a[0]), "r"(a[1]), "r"(a[2]), "r"(a[3]),
          "r"(b[0]), "r"(b[1]));
}

DEV_INLINE uint32_t smem_u32(const void* p) {
    uint32_t a;
    asm("{ .reg .u64 t; cvta.to.shared.u64 t, %1; cvt.u32.u64 %0, t; }"
        : "=r"(a) : "l"(p));
    return a;
}

DEV_INLINE void cp16(uint32_t dst, const void* src) {
    asm volatile("cp.async.cg.shared.global [%0], [%1], 16;" :: "r"(dst), "l"(src));
}
#define CP_COMMIT() asm volatile("cp.async.commit_group;" ::: "memory")
#define CP_WAIT0()  asm volatile("cp.async.wait_group 0;" ::: "memory")

// ---------------- tf32 rounding pass (weights) ---------------------------
__global__ void round_tf32_kernel(const float* __restrict__ src,
                                  float* __restrict__ dst, int n4)
{
    int i = blockIdx.x * blockDim.x + threadIdx.x;
    if (i >= n4) return;
    float4 v = ((const float4*)src)[i];
    ((uint4*)dst)[i] = make_uint4(f2tf(v.x), f2tf(v.y), f2tf(v.z), f2tf(v.w));
}

// ---------------- LayerNorm (emits tf32-rounded output) ------------------
__global__ void ln_kernel(const float* __restrict__ x,
                          const float* __restrict__ g,
                          const float* __restrict__ b,
                          float* __restrict__ y)
{
    __shared__ float red[8];
    int row = blockIdx.x;
    int t = threadIdx.x;
    const float4* xr = (const float4*)(x + (size_t)row * Dc);
    float4 v = xr[t];

    float s = v.x + v.y + v.z + v.w;
    s = warp_sum(s);
    if ((t & 31) == 0) red[t >> 5] = s;
    __syncthreads();
    float tot = 0.f;
    #pragma unroll
    for (int i = 0; i < 8; i++) tot += red[i];
    float mean = tot * (1.0f / Dc);
    __syncthreads();

    float dx = v.x - mean, dy = v.y - mean, dz = v.z - mean, dw = v.w - mean;
    float s2 = dx*dx + dy*dy + dz*dz + dw*dw;
    s2 = warp_sum(s2);
    if ((t & 31) == 0) red[t >> 5] = s2;
    __syncthreads();
    float tot2 = 0.f;
    #pragma unroll
    for (int i = 0; i < 8; i++) tot2 += red[i];
    float rstd = rsqrtf(tot2 * (1.0f / Dc) + 1e-5f);

    float4 gg = ((const float4*)g)[t];
    float4 bb = ((const float4*)b)[t];
    float4 o;
    o.x = f2tf_f(dx * rstd * gg.x + bb.x);
    o.y = f2tf_f(dy * rstd * gg.y + bb.y);
    o.z = f2tf_f(dz * rstd * gg.z + bb.z);
    o.w = f2tf_f(dw * rstd * gg.w + bb.w);
    ((float4*)(y + (size_t)row * Dc))[t] = o;
}

// ---------------- residual + Poincare projection over full row ----------
__global__ void resproj_kernel(const float* __restrict__ x,
                               const float* __restrict__ add,
                               float* __restrict__ out)
{
    __shared__ float red[8];
    int row = blockIdx.x;
    int t = threadIdx.x;
    float4 a = ((const float4*)(x   + (size_t)row * Dc))[t];
    float4 c = ((const float4*)(add + (size_t)row * Dc))[t];
    float4 v = make_float4(a.x + c.x, a.y + c.y, a.z + c.z, a.w + c.w);

    float s = v.x*v.x + v.y*v.y + v.z*v.z + v.w*v.w;
    s = warp_sum(s);
    if ((t & 31) == 0) red[t >> 5] = s;
    __syncthreads();
    float tot = 0.f;
    #pragma unroll
    for (int i = 0; i < 8; i++) tot += red[i];
    float n = sqrtf(tot);
    const float maxn = 1.0f - 1e-5f;
    float sc = (n > maxn) ? (maxn / n) : 1.0f;

    v.x *= sc; v.y *= sc; v.z *= sc; v.w *= sc;
    ((float4*)(out + (size_t)row * Dc))[t] = v;
}

// ---------------- tf32 GEMM, cp.async pipelined, pre-rounded operands ----
// C[M,N] = A[M,K] @ B[N,K]^T + bias (EPI=1: exact GELU + tf32-round output).
// CTA 128x128, BK=32, 256 threads = 8 warps (4M x 2N), warp 32x64.
// Natural k-contiguous smem (cp.async-filled), row stride 40 words.
// Consumer-side k-slot permutation: mma slot pair (kq, kq+4) sources
// k = (2kq, 2kq+1) -> one conflict-free LDS.64 per fragment pair.
constexpr int GLD2  = 40;                 // row stride in words (160B)
constexpr int MATW2 = 128 * GLD2;         // 5120 words per matrix
constexpr int STW   = 2 * MATW2;          // A + B per stage (words)
constexpr int G_SMEM = 2 * STW * 4;       // 81920 bytes

template<int EPI>
__global__ __launch_bounds__(256, 2)
void gemm_tf32(const float* __restrict__ A, const float* __restrict__ B,
               const float* __restrict__ bias, float* __restrict__ C,
               int M, int N, int K)
{
    extern __shared__ uint32_t sh[];
    uint32_t shb = smem_u32(sh);

    int tid = threadIdx.x;
    int bm = blockIdx.y * 128, bn = blockIdx.x * 128;
    int lane = tid & 31, warp = tid >> 5;
    int wm = (warp & 3) * 32;
    int wn = (warp >> 2) * 64;
    int grp = lane >> 2, kq = lane & 3;

    float acc[2][8][4];
    #pragma unroll
    for (int mt = 0; mt < 2; mt++)
        #pragma unroll
        for (int nt = 0; nt < 8; nt++)
            #pragma unroll
            for (int r = 0; r < 4; r++) acc[mt][nt][r] = 0.f;

    // fill mapping: 2 threads per row, 16 floats (4 x 16B) each
    int frow = tid >> 1;
    int fc   = (tid & 1) * 16;
    const float* Ap = A + (size_t)(bm + frow) * K + fc;
    const float* Bp = B + (size_t)(bn + frow) * K + fc;
    uint32_t sA = shb + (frow * GLD2 + fc) * 4;
    uint32_t sB = sA + MATW2 * 4;

    const int nk = K / 32;

    // prologue: stage 0
    {
        #pragma unroll
        for (int j = 0; j < 4; j++) {
            cp16(sA + j * 16, Ap + j * 4);
            cp16(sB + j * 16, Bp + j * 4);
        }
        CP_COMMIT();
    }

    // fragment row bases (word offsets)
    uint32_t ra0 = (wm + grp)      * GLD2 + 2 * kq;
    uint32_t ra1 = (wm + grp + 8)  * GLD2 + 2 * kq;
    uint32_t ra2 = (wm + grp + 16) * GLD2 + 2 * kq;
    uint32_t ra3 = (wm + grp + 24) * GLD2 + 2 * kq;
    uint32_t rb  = (wn + grp)      * GLD2 + 2 * kq;

    for (int it = 0; it < nk; it++) {
        CP_WAIT0();
        __syncthreads();
        if (it + 1 < nk) {
            uint32_t d = ((it + 1) & 1) * STW * 4;
            const float* An = Ap + (it + 1) * 32;
            const float* Bn = Bp + (it + 1) * 32;
            #pragma unroll
            for (int j = 0; j < 4; j++) {
                cp16(sA + d + j * 16, An + j * 4);
                cp16(sB + d + j * 16, Bn + j * 4);
            }
            CP_COMMIT();
        }
        const uint32_t* Ac = sh + (it & 1) * STW;
        const uint32_t* Bcs = Ac + MATW2;

        #pragma unroll
        for (int kk = 0; kk < 4; kk++) {
            int co = kk * 8;
            uint2 x0 = *(const uint2*)(Ac + ra0 + co);
            uint2 x1 = *(const uint2*)(Ac + ra1 + co);
            uint2 x2 = *(const uint2*)(Ac + ra2 + co);
            uint2 x3 = *(const uint2*)(Ac + ra3 + co);
            uint32_t av0[4] = {x0.x, x1.x, x0.y, x1.y};
            uint32_t av1[4] = {x2.x, x3.x, x2.y, x3.y};
            #pragma unroll
            for (int nt = 0; nt < 8; nt++) {
                uint2 bv = *(const uint2*)(Bcs + rb + nt * 8 * GLD2 + co);
                uint32_t b2[2] = {bv.x, bv.y};
                mma_tf32(acc[0][nt], av0, b2);
                mma_tf32(acc[1][nt], av1, b2);
            }
        }
        // next iteration's top __syncthreads protects buffer reuse
    }

    // epilogue
    #pragma unroll
    for (int mt = 0; mt < 2; mt++) {
        int row0 = bm + wm + mt * 16 + grp;
        #pragma unroll
        for (int nt = 0; nt < 8; nt++) {
            int col = bn + wn + nt * 8 + kq * 2;
            float b0 = bias[col], b1 = bias[col + 1];
            float v0 = acc[mt][nt][0] + b0;
            float v1 = acc[mt][nt][1] + b1;
            float v2 = acc[mt][nt][2] + b0;
            float v3 = acc[mt][nt][3] + b1;
            if (EPI == 1) {
                v0 = f2tf_f(0.5f * v0 * (1.0f + erff(v0 * 0.70710678118654752f)));
                v1 = f2tf_f(0.5f * v1 * (1.0f + erff(v1 * 0.70710678118654752f)));
                v2 = f2tf_f(0.5f * v2 * (1.0f + erff(v2 * 0.70710678118654752f)));
                v3 = f2tf_f(0.5f * v3 * (1.0f + erff(v3 * 0.70710678118654752f)));
            }
            *(float2*)(C + (size_t)row0 * N + col)       = make_float2(v0, v1);
            *(float2*)(C + (size_t)(row0 + 8) * N + col) = make_float2(v2, v3);
        }
    }
}

// ---------------- head split + projection + prescaled q/k2 --------------
__global__ void qkv_tr_kernel(const float* __restrict__ yq,
                              const float* __restrict__ yk,
                              const float* __restrict__ yv,
                              float* __restrict__ q, float* __restrict__ k,
                              float* __restrict__ v, float* __restrict__ k2)
{
    int bl = blockIdx.x;
    int b = bl >> 11;
    int l = bl & 2047;
    int w = threadIdx.x >> 5;
    int lane = threadIdx.x & 31;
    const float maxn = 1.0f - 1e-5f;

    size_t src = (size_t)bl * Dc + w * HDc + lane * 2;
    size_t dst = ((size_t)(b * Hc + w) * Lc + l) * HDc + lane * 2;

    float2 qv = *(const float2*)(yq + src);
    float sq = warp_sum(qv.x*qv.x + qv.y*qv.y);
    float nq = sqrtf(sq);
    float scq = ((nq > maxn) ? (maxn / nq) : 1.0f) * 0.25f;
    *(float2*)(q + dst) = make_float2(qv.x * scq, qv.y * scq);

    float2 kv = *(const float2*)(yk + src);
    float sk = warp_sum(kv.x*kv.x + kv.y*kv.y);
    float nk = sqrtf(sk);
    float sck = (nk > maxn) ? (maxn / nk) : 1.0f;
    *(float2*)(k + dst) = make_float2(kv.x * sck, kv.y * sck);
    if (lane == 0) k2[(size_t)(b * Hc + w) * Lc + l] = sk * sck * sck * 0.125f;

    *(float2*)(v + dst) = *(const float2*)(yv + src);
}

// ---------------- flash attention, tf32 mma (R3-proven; rounds output) ---
constexpr int ALD = 68;
constexpr int ATT_SMEM = (128 * ALD + 64 * ALD + 64 * ALD) * 4 + 64 * 4;

__global__ __launch_bounds__(256, 2)
void attn_mma_kernel(const float* __restrict__ q, const float* __restrict__ k,
                     const float* __restrict__ v, const float* __restrict__ k2,
                     float* __restrict__ out)
{
    extern __shared__ uint32_t usm[];
    uint32_t* Qs = usm;
    uint32_t* Ks = Qs + 128 * ALD;
    uint32_t* Vs = Ks + 64 * ALD;
    float* k2s   = (float*)(Vs + 64 * ALD);

    int qb = blockIdx.x, bh = blockIdx.y;
    int tid = threadIdx.x, lane = tid & 31, warp = tid >> 5;
    int wm = warp * 16, grp = lane >> 2, kq = lane & 3;

    const float* qbase = q + ((size_t)bh * Lc + qb * 128) * HDc;
    #pragma unroll
    for (int it = 0; it < 8; it++) {
        int idx = tid + it * 256;
        int r = idx >> 4, c4 = (idx & 15) * 4;
        float4 t = *(const float4*)(qbase + r * HDc + c4);
        uint32_t* p = &Qs[r * ALD + c4];
        p[0] = f2tf(t.x); p[1] = f2tf(t.y); p[2] = f2tf(t.z); p[3] = f2tf(t.w);
    }
    __syncthreads();

    uint32_t qf[8][4];
    #pragma unroll
    for (int kk = 0; kk < 8; kk++) {
        int kb = kk * 8 + kq, m = wm + grp;
        qf[kk][0] = Qs[m * ALD + kb];
        qf[kk][1] = Qs[(m + 8) * ALD + kb];
        qf[kk][2] = Qs[m * ALD + kb + 4];
        qf[kk][3] = Qs[(m + 8) * ALD + kb + 4];
    }

    float o[8][4];
    #pragma unroll
    for (int nt = 0; nt < 8; nt++)
        #pragma unroll
        for (int r = 0; r < 4; r++) o[nt][r] = 0.f;
    float m0 = -INFINITY, m1 = -INFINITY, l0 = 0.f, l1 = 0.f;

    for (int jb = 0; jb < Lc / 64; jb++) {
        __syncthreads();
        const float* kb_ = k + ((size_t)bh * Lc + jb * 64) * HDc;
        const float* vb_ = v + ((size_t)bh * Lc + jb * 64) * HDc;
        #pragma unroll
        for (int it = 0; it < 4; it++) {
            int idx = tid + it * 256;
            int r = idx >> 4, c4 = (idx & 15) * 4;
            float4 a = *(const float4*)(kb_ + r * HDc + c4);
            uint32_t* kp = &Ks[r * ALD + c4];
            kp[0] = f2tf(a.x); kp[1] = f2tf(a.y); kp[2] = f2tf(a.z); kp[3] = f2tf(a.w);
            float4 bv = *(const float4*)(vb_ + r * HDc + c4);
            uint32_t* vp = &Vs[r * ALD + c4];
            vp[0] = f2tf(bv.x); vp[1] = f2tf(bv.y); vp[2] = f2tf(bv.z); vp[3] = f2tf(bv.w);
        }
        if (tid < 64) k2s[tid] = k2[(size_t)bh * Lc + jb * 64 + tid];
        __syncthreads();

        float s[8][4];
        #pragma unroll
        for (int nt = 0; nt < 8; nt++)
            #pragma unroll
            for (int r = 0; r < 4; r++) s[nt][r] = 0.f;

        #pragma unroll
        for (int kk = 0; kk < 8; kk++) {
            int kb = kk * 8 + kq;
            uint32_t b[8][2];
            #pragma unroll
            for (int nt = 0; nt < 8; nt++) {
                int n = nt * 8 + grp;
                b[nt][0] = Ks[n * ALD + kb];
                b[nt][1] = Ks[n * ALD + kb + 4];
            }
            #pragma unroll
            for (int nt = 0; nt < 8; nt++)
                mma_tf32(s[nt], qf[kk], b[nt]);
        }

        #pragma unroll
        for (int nt = 0; nt < 8; nt++) {
            float ka = k2s[nt * 8 + kq * 2];
            float kbv = k2s[nt * 8 + kq * 2 + 1];
            s[nt][0] -= ka; s[nt][1] -= kbv;
            s[nt][2] -= ka; s[nt][3] -= kbv;
        }

        float rm0 = -INFINITY, rm1 = -INFINITY;
        #pragma unroll
        for (int nt = 0; nt < 8; nt++) {
            rm0 = fmaxf(rm0, fmaxf(s[nt][0], s[nt][1]));
            rm1 = fmaxf(rm1, fmaxf(s[nt][2], s[nt][3]));
        }
        #pragma unroll
        for (int ofs = 1; ofs < 4; ofs <<= 1) {
            rm0 = fmaxf(rm0, __shfl_xor_sync(0xffffffffu, rm0, ofs));
            rm1 = fmaxf(rm1, __shfl_xor_sync(0xffffffffu, rm1, ofs));
        }
        float mn0 = fmaxf(m0, rm0), mn1 = fmaxf(m1, rm1);
        float al0 = __expf(m0 - mn0), al1 = __expf(m1 - mn1);
        float rs0 = 0.f, rs1 = 0.f;

        uint32_t* Ps = Qs;
        int prow = (wm + grp) * ALD + kq * 2;
        #pragma unroll
        for (int nt = 0; nt < 8; nt++) {
            float p0 = __expf(s[nt][0] - mn0);
            float p1 = __expf(s[nt][1] - mn0);
            float p2 = __expf(s[nt][2] - mn1);
            float p3 = __expf(s[nt][3] - mn1);
            rs0 += p0 + p1; rs1 += p2 + p3;
            Ps[prow + nt * 8]               = f2tf(p0);
            Ps[prow + nt * 8 + 1]           = f2tf(p1);
            Ps[prow + 8 * ALD + nt * 8]     = f2tf(p2);
            Ps[prow + 8 * ALD + nt * 8 + 1] = f2tf(p3);
        }
        #pragma unroll
        for (int ofs = 1; ofs < 4; ofs <<= 1) {
            rs0 += __shfl_xor_sync(0xffffffffu, rs0, ofs);
            rs1 += __shfl_xor_sync(0xffffffffu, rs1, ofs);
        }
        l0 = l0 * al0 + rs0; m0 = mn0;
        l1 = l1 * al1 + rs1; m1 = mn1;
        #pragma unroll
        for (int nt = 0; nt < 8; nt++) {
            o[nt][0] *= al0; o[nt][1] *= al0;
            o[nt][2] *= al1; o[nt][3] *= al1;
        }
        __syncwarp();

        #pragma unroll
        for (int kk = 0; kk < 8; kk++) {
            int kb = kk * 8 + kq, m = wm + grp;
            uint32_t a[4];
            a[0] = Ps[m * ALD + kb];
            a[1] = Ps[(m + 8) * ALD + kb];
            a[2] = Ps[m * ALD + kb + 4];
            a[3] = Ps[(m + 8) * ALD + kb + 4];
            uint32_t b[8][2];
            #pragma unroll
            for (int nt = 0; nt < 8; nt++) {
                int n = nt * 8 + grp;
                b[nt][0] = Vs[kb * ALD + n];
                b[nt][1] = Vs[(kb + 4) * ALD + n];
            }
            #pragma unroll
            for (int nt = 0; nt < 8; nt++)
                mma_tf32(o[nt], a, b[nt]);
        }
    }

    float inv0 = 1.0f / l0, inv1 = 1.0f / l1;
    int b_ = bh >> 4, h = bh & 15;
    int row0 = qb * 128 + wm + grp;
    #pragma unroll
    for (int nt = 0; nt < 8; nt++) {
        int col = h * HDc + nt * 8 + kq * 2;
        *(float2*)(out + ((size_t)(b_ * Lc + row0)) * Dc + col) =
            make_float2(f2tf_f(o[nt][0] * inv0), f2tf_f(o[nt][1] * inv0));
        *(float2*)(out + ((size_t)(b_ * Lc + row0 + 8)) * Dc + col) =
            make_float2(f2tf_f(o[nt][2] * inv1), f2tf_f(o[nt][3] * inv1));
    }
}

// -------------------------------- host ----------------------------------
static float* sym_ptr(const void* sym) {
    void* p = nullptr;
    cudaGetSymbolAddress(&p, sym);
    return (float*)p;
}

extern "C" void kernel_launch(void* const* d_in, const int* in_sizes, int n_in,
                              void* d_out, int out_size)
{
    const float* x   = (const float*)d_in[0];
    const float* wq  = (const float*)d_in[1];
    const float* bq  = (const float*)d_in[2];
    const float* wk  = (const float*)d_in[3];
    const float* bk  = (const float*)d_in[4];
    const float* wv  = (const float*)d_in[5];
    const float* bv  = (const float*)d_in[6];
    const float* wo  = (const float*)d_in[7];
    const float* bo  = (const float*)d_in[8];
    const float* g1  = (const float*)d_in[9];
    const float* b1  = (const float*)d_in[10];
    const float* g2  = (const float*)d_in[11];
    const float* b2  = (const float*)d_in[12];
    const float* w1  = (const float*)d_in[13];
    const float* bf1 = (const float*)d_in[14];
    const float* w2  = (const float*)d_in[15];
    const float* bf2 = (const float*)d_in[16];
    float* out = (float*)d_out;

    float* xn  = sym_ptr(g_xn);
    float* yq  = sym_ptr(g_yq);
    float* yk  = sym_ptr(g_yk);
    float* yv  = sym_ptr(g_yv);
    float* qd  = sym_ptr(g_q);
    float* kd  = sym_ptr(g_k);
    float* vd  = sym_ptr(g_v);
    float* k2d = sym_ptr(g_k2);
    float* att = sym_ptr(g_att);
    float* od  = sym_ptr(g_o);
    float* x2  = sym_ptr(g_x2);
    float* ffh = sym_ptr(g_ffh);
    float* f2  = sym_ptr(g_f2);
    float* twq = sym_ptr(g_twq);
    float* twk = sym_ptr(g_twk);
    float* twv = sym_ptr(g_twv);
    float* two = sym_ptr(g_two);
    float* tw1 = sym_ptr(g_tw1);
    float* tw2 = sym_ptr(g_tw2);

    cudaFuncSetAttribute(gemm_tf32<0>, cudaFuncAttributeMaxDynamicSharedMemorySize, G_SMEM);
    cudaFuncSetAttribute(gemm_tf32<1>, cudaFuncAttributeMaxDynamicSharedMemorySize, G_SMEM);
    cudaFuncSetAttribute(attn_mma_kernel, cudaFuncAttributeMaxDynamicSharedMemorySize, ATT_SMEM);

    // pre-round weights to tf32 (bit patterns valid for direct mma input)
    int nDD = (Dc * Dc) / 4, nF = (DFc * Dc) / 4;
    round_tf32_kernel<<<(nDD + 255) / 256, 256>>>(wq, twq, nDD);
    round_tf32_kernel<<<(nDD + 255) / 256, 256>>>(wk, twk, nDD);
    round_tf32_kernel<<<(nDD + 255) / 256, 256>>>(wv, twv, nDD);
    round_tf32_kernel<<<(nDD + 255) / 256, 256>>>(wo, two, nDD);
    round_tf32_kernel<<<(nF + 255) / 256, 256>>>(w1, tw1, nF);
    round_tf32_kernel<<<(nF + 255) / 256, 256>>>(w2, tw2, nF);

    dim3 gProj(Dc / 128, Mc / 128);    // (8, 32)
    dim3 gFfn1(DFc / 128, Mc / 128);   // (32, 32)

    ln_kernel<<<Mc, 256>>>(x, g1, b1, xn);
    gemm_tf32<0><<<gProj, 256, G_SMEM>>>(xn, twq, bq, yq, Mc, Dc, Dc);
    gemm_tf32<0><<<gProj, 256, G_SMEM>>>(xn, twk, bk, yk, Mc, Dc, Dc);
    gemm_tf32<0><<<gProj, 256, G_SMEM>>>(xn, twv, bv, yv, Mc, Dc, Dc);
    qkv_tr_kernel<<<Mc, 512>>>(yq, yk, yv, qd, kd, vd, k2d);

    attn_mma_kernel<<<dim3(Lc / 128, Bc * Hc), 256, ATT_SMEM>>>(qd, kd, vd, k2d, att);

    gemm_tf32<0><<<gProj, 256, G_SMEM>>>(att, two, bo, od, Mc, Dc, Dc);
    resproj_kernel<<<Mc, 256>>>(x, od, x2);
    ln_kernel<<<Mc, 256>>>(x2, g2, b2, xn);
    gemm_tf32<1><<<gFfn1, 256, G_SMEM>>>(xn, tw1, bf1, ffh, Mc, DFc, Dc);
    gemm_tf32<0><<<gProj, 256, G_SMEM>>>(ffh, tw2, bf2, f2, Mc, Dc, DFc);
    resproj_kernel<<<Mc, 256>>>(x2, f2, out);
}

// round 7
// speedup vs baseline: 1.2786x; 1.2786x over previous
#include <cuda_runtime.h>
#include <math.h>
#include <stdint.h>

#define DEV_INLINE __device__ __forceinline__

// Problem dims
constexpr int Bc = 2;
constexpr int Lc = 2048;
constexpr int Dc = 1024;
constexpr int Hc = 16;
constexpr int HDc = 64;
constexpr int Mc = Bc * Lc;      // 4096 rows
constexpr int DFc = 4096;        // FFN hidden

// -------- scratch (static device globals; no allocation at runtime) --------
__device__ float g_xn [Mc * Dc];
__device__ float g_yq [Mc * Dc];
__device__ float g_yk [Mc * Dc];
__device__ float g_yv [Mc * Dc];
__device__ float g_q  [Mc * Dc];
__device__ float g_k  [Mc * Dc];
__device__ float g_v  [Mc * Dc];
__device__ float g_k2 [Bc * Hc * Lc];
__device__ float g_att[Mc * Dc];
__device__ float g_o  [Mc * Dc];
__device__ float g_x2 [Mc * Dc];
__device__ float g_ffh[(size_t)Mc * DFc];
__device__ float g_f2 [Mc * Dc];
// tf32-rounded weights
__device__ float g_twq[Dc * Dc];
__device__ float g_twk[Dc * Dc];
__device__ float g_twv[Dc * Dc];
__device__ float g_two[Dc * Dc];
__device__ float g_tw1[(size_t)DFc * Dc];
__device__ float g_tw2[(size_t)Dc * DFc];

DEV_INLINE float warp_sum(float v) {
    #pragma unroll
    for (int o = 16; o > 0; o >>= 1) v += __shfl_xor_sync(0xffffffffu, v, o);
    return v;
}

DEV_INLINE uint32_t f2tf(float x) {
    uint32_t r;
    asm("cvt.rna.tf32.f32 %0, %1;" : "=r"(r) : "f"(x));
    return r;
}
DEV_INLINE float f2tf_f(float x) { return __uint_as_float(f2tf(x)); }

DEV_INLINE void mma_tf32(float* c, const uint32_t* a, const uint32_t* b) {
    asm volatile(
        "mma.sync.aligned.m16n8k8.row.col.f32.tf32.tf32.f32 "
        "{%0,%1,%2,%3}, {%4,%5,%6,%7}, {%8,%9}, {%0,%1,%2,%3};\n"
        : "+f"(c[0]), "+f"(c[1]), "+f"(c[2]), "+f"(c[3])
        : "r"(a[0]), "r"(a[1]), "r"(a[2]), "r"(a[3]),
          "r"(b[0]), "r"(b[1]));
}

// ---------------- tf32 rounding pass (weights) ---------------------------
__global__ void round_tf32_kernel(const float* __restrict__ src,
                                  float* __restrict__ dst, int n4)
{
    int i = blockIdx.x * blockDim.x + threadIdx.x;
    if (i >= n4) return;
    float4 v = ((const float4*)src)[i];
    ((uint4*)dst)[i] = make_uint4(f2tf(v.x), f2tf(v.y), f2tf(v.z), f2tf(v.w));
}

// ---------------- LayerNorm (emits tf32-rounded output) ------------------
__global__ void ln_kernel(const float* __restrict__ x,
                          const float* __restrict__ g,
                          const float* __restrict__ b,
                          float* __restrict__ y)
{
    __shared__ float red[8];
    int row = blockIdx.x;
    int t = threadIdx.x;
    const float4* xr = (const float4*)(x + (size_t)row * Dc);
    float4 v = xr[t];

    float s = v.x + v.y + v.z + v.w;
    s = warp_sum(s);
    if ((t & 31) == 0) red[t >> 5] = s;
    __syncthreads();
    float tot = 0.f;
    #pragma unroll
    for (int i = 0; i < 8; i++) tot += red[i];
    float mean = tot * (1.0f / Dc);
    __syncthreads();

    float dx = v.x - mean, dy = v.y - mean, dz = v.z - mean, dw = v.w - mean;
    float s2 = dx*dx + dy*dy + dz*dz + dw*dw;
    s2 = warp_sum(s2);
    if ((t & 31) == 0) red[t >> 5] = s2;
    __syncthreads();
    float tot2 = 0.f;
    #pragma unroll
    for (int i = 0; i < 8; i++) tot2 += red[i];
    float rstd = rsqrtf(tot2 * (1.0f / Dc) + 1e-5f);

    float4 gg = ((const float4*)g)[t];
    float4 bb = ((const float4*)b)[t];
    float4 o;
    o.x = f2tf_f(dx * rstd * gg.x + bb.x);
    o.y = f2tf_f(dy * rstd * gg.y + bb.y);
    o.z = f2tf_f(dz * rstd * gg.z + bb.z);
    o.w = f2tf_f(dw * rstd * gg.w + bb.w);
    ((float4*)(y + (size_t)row * Dc))[t] = o;
}

// ---------------- residual + Poincare projection over full row ----------
__global__ void resproj_kernel(const float* __restrict__ x,
                               const float* __restrict__ add,
                               float* __restrict__ out)
{
    __shared__ float red[8];
    int row = blockIdx.x;
    int t = threadIdx.x;
    float4 a = ((const float4*)(x   + (size_t)row * Dc))[t];
    float4 c = ((const float4*)(add + (size_t)row * Dc))[t];
    float4 v = make_float4(a.x + c.x, a.y + c.y, a.z + c.z, a.w + c.w);

    float s = v.x*v.x + v.y*v.y + v.z*v.z + v.w*v.w;
    s = warp_sum(s);
    if ((t & 31) == 0) red[t >> 5] = s;
    __syncthreads();
    float tot = 0.f;
    #pragma unroll
    for (int i = 0; i < 8; i++) tot += red[i];
    float n = sqrtf(tot);
    const float maxn = 1.0f - 1e-5f;
    float sc = (n > maxn) ? (maxn / n) : 1.0f;

    v.x *= sc; v.y *= sc; v.z *= sc; v.w *= sc;
    ((float4*)(out + (size_t)row * Dc))[t] = v;
}

// ---------------- tf32 tensor-core GEMM (R3 structure, copy-only fill) ---
// C[M,N] = A[M,K] @ B[N,K]^T + bias, optional exact GELU (tf32-rounded out).
// Inputs A and B are ALREADY tf32-rounded (producers round). Fill is a pure
// LDG.128 -> STS.128 copy. Everything else identical to the proven R3 GEMM.
constexpr int GLD = 36;

template<int EPI>
__global__ __launch_bounds__(256)
void gemm_tf32(const float* __restrict__ A, const float* __restrict__ B,
               const float* __restrict__ bias, float* __restrict__ C,
               int M, int N, int K)
{
    __shared__ uint32_t As[128 * GLD];
    __shared__ uint32_t Bs[128 * GLD];

    int tid = threadIdx.x;
    int bm = blockIdx.y * 128, bn = blockIdx.x * 128;
    int lane = tid & 31, warp = tid >> 5;
    int wm = (warp & 3) * 32;
    int wn = (warp >> 2) * 64;
    int grp = lane >> 2, kq = lane & 3;

    float acc[2][8][4];
    #pragma unroll
    for (int mt = 0; mt < 2; mt++)
        #pragma unroll
        for (int nt = 0; nt < 8; nt++)
            #pragma unroll
            for (int r = 0; r < 4; r++) acc[mt][nt][r] = 0.f;

    int lrow = tid >> 3;
    int lkc  = (tid & 7) * 4;

    for (int k0 = 0; k0 < K; k0 += 32) {
        #pragma unroll
        for (int i = 0; i < 4; i++) {
            int r = lrow + i * 32;
            *(uint4*)&As[r * GLD + lkc] =
                *(const uint4*)(A + (size_t)(bm + r) * K + k0 + lkc);
            *(uint4*)&Bs[r * GLD + lkc] =
                *(const uint4*)(B + (size_t)(bn + r) * K + k0 + lkc);
        }
        __syncthreads();

        #pragma unroll
        for (int kk = 0; kk < 4; kk++) {
            int kb = kk * 8 + kq;
            uint32_t a[2][4], b[8][2];
            #pragma unroll
            for (int mt = 0; mt < 2; mt++) {
                int m = wm + mt * 16 + grp;
                a[mt][0] = As[(m    ) * GLD + kb];
                a[mt][1] = As[(m + 8) * GLD + kb];
                a[mt][2] = As[(m    ) * GLD + kb + 4];
                a[mt][3] = As[(m + 8) * GLD + kb + 4];
            }
            #pragma unroll
            for (int nt = 0; nt < 8; nt++) {
                int n = wn + nt * 8 + grp;
                b[nt][0] = Bs[n * GLD + kb];
                b[nt][1] = Bs[n * GLD + kb + 4];
            }
            #pragma unroll
            for (int mt = 0; mt < 2; mt++)
                #pragma unroll
                for (int nt = 0; nt < 8; nt++)
                    mma_tf32(acc[mt][nt], a[mt], b[nt]);
        }
        __syncthreads();
    }

    #pragma unroll
    for (int mt = 0; mt < 2; mt++) {
        int row0 = bm + wm + mt * 16 + grp;
        #pragma unroll
        for (int nt = 0; nt < 8; nt++) {
            int col = bn + wn + nt * 8 + kq * 2;
            float b0 = bias[col], b1 = bias[col + 1];
            float v0 = acc[mt][nt][0] + b0;
            float v1 = acc[mt][nt][1] + b1;
            float v2 = acc[mt][nt][2] + b0;
            float v3 = acc[mt][nt][3] + b1;
            if (EPI == 1) {
                v0 = f2tf_f(0.5f * v0 * (1.0f + erff(v0 * 0.70710678118654752f)));
                v1 = f2tf_f(0.5f * v1 * (1.0f + erff(v1 * 0.70710678118654752f)));
                v2 = f2tf_f(0.5f * v2 * (1.0f + erff(v2 * 0.70710678118654752f)));
                v3 = f2tf_f(0.5f * v3 * (1.0f + erff(v3 * 0.70710678118654752f)));
            }
            *(float2*)(C + (size_t)row0 * N + col)       = make_float2(v0, v1);
            *(float2*)(C + (size_t)(row0 + 8) * N + col) = make_float2(v2, v3);
        }
    }
}

// ---------------- head split + projection + prescaled q/k2 --------------
__global__ void qkv_tr_kernel(const float* __restrict__ yq,
                              const float* __restrict__ yk,
                              const float* __restrict__ yv,
                              float* __restrict__ q, float* __restrict__ k,
                              float* __restrict__ v, float* __restrict__ k2)
{
    int bl = blockIdx.x;
    int b = bl >> 11;
    int l = bl & 2047;
    int w = threadIdx.x >> 5;
    int lane = threadIdx.x & 31;
    const float maxn = 1.0f - 1e-5f;

    size_t src = (size_t)bl * Dc + w * HDc + lane * 2;
    size_t dst = ((size_t)(b * Hc + w) * Lc + l) * HDc + lane * 2;

    float2 qv = *(const float2*)(yq + src);
    float sq = warp_sum(qv.x*qv.x + qv.y*qv.y);
    float nq = sqrtf(sq);
    float scq = ((nq > maxn) ? (maxn / nq) : 1.0f) * 0.25f;
    *(float2*)(q + dst) = make_float2(qv.x * scq, qv.y * scq);

    float2 kv = *(const float2*)(yk + src);
    float sk = warp_sum(kv.x*kv.x + kv.y*kv.y);
    float nk = sqrtf(sk);
    float sck = (nk > maxn) ? (maxn / nk) : 1.0f;
    *(float2*)(k + dst) = make_float2(kv.x * sck, kv.y * sck);
    if (lane == 0) k2[(size_t)(b * Hc + w) * Lc + l] = sk * sck * sck * 0.125f;

    *(float2*)(v + dst) = *(const float2*)(yv + src);
}

// ---------------- flash attention, tf32 mma (R3-proven; rounds output) ---
constexpr int ALD = 68;
constexpr int ATT_SMEM = (128 * ALD + 64 * ALD + 64 * ALD) * 4 + 64 * 4;

__global__ __launch_bounds__(256, 2)
void attn_mma_kernel(const float* __restrict__ q, const float* __restrict__ k,
                     const float* __restrict__ v, const float* __restrict__ k2,
                     float* __restrict__ out)
{
    extern __shared__ uint32_t usm[];
    uint32_t* Qs = usm;
    uint32_t* Ks = Qs + 128 * ALD;
    uint32_t* Vs = Ks + 64 * ALD;
    float* k2s   = (float*)(Vs + 64 * ALD);

    int qb = blockIdx.x, bh = blockIdx.y;
    int tid = threadIdx.x, lane = tid & 31, warp = tid >> 5;
    int wm = warp * 16, grp = lane >> 2, kq = lane & 3;

    const float* qbase = q + ((size_t)bh * Lc + qb * 128) * HDc;
    #pragma unroll
    for (int it = 0; it < 8; it++) {
        int idx = tid + it * 256;
        int r = idx >> 4, c4 = (idx & 15) * 4;
        float4 t = *(const float4*)(qbase + r * HDc + c4);
        uint32_t* p = &Qs[r * ALD + c4];
        p[0] = f2tf(t.x); p[1] = f2tf(t.y); p[2] = f2tf(t.z); p[3] = f2tf(t.w);
    }
    __syncthreads();

    uint32_t qf[8][4];
    #pragma unroll
    for (int kk = 0; kk < 8; kk++) {
        int kb = kk * 8 + kq, m = wm + grp;
        qf[kk][0] = Qs[m * ALD + kb];
        qf[kk][1] = Qs[(m + 8) * ALD + kb];
        qf[kk][2] = Qs[m * ALD + kb + 4];
        qf[kk][3] = Qs[(m + 8) * ALD + kb + 4];
    }

    float o[8][4];
    #pragma unroll
    for (int nt = 0; nt < 8; nt++)
        #pragma unroll
        for (int r = 0; r < 4; r++) o[nt][r] = 0.f;
    float m0 = -INFINITY, m1 = -INFINITY, l0 = 0.f, l1 = 0.f;

    for (int jb = 0; jb < Lc / 64; jb++) {
        __syncthreads();
        const float* kb_ = k + ((size_t)bh * Lc + jb * 64) * HDc;
        const float* vb_ = v + ((size_t)bh * Lc + jb * 64) * HDc;
        #pragma unroll
        for (int it = 0; it < 4; it++) {
            int idx = tid + it * 256;
            int r = idx >> 4, c4 = (idx & 15) * 4;
            float4 a = *(const float4*)(kb_ + r * HDc + c4);
            uint32_t* kp = &Ks[r * ALD + c4];
            kp[0] = f2tf(a.x); kp[1] = f2tf(a.y); kp[2] = f2tf(a.z); kp[3] = f2tf(a.w);
            float4 bv = *(const float4*)(vb_ + r * HDc + c4);
            uint32_t* vp = &Vs[r * ALD + c4];
            vp[0] = f2tf(bv.x); vp[1] = f2tf(bv.y); vp[2] = f2tf(bv.z); vp[3] = f2tf(bv.w);
        }
        if (tid < 64) k2s[tid] = k2[(size_t)bh * Lc + jb * 64 + tid];
        __syncthreads();

        float s[8][4];
        #pragma unroll
        for (int nt = 0; nt < 8; nt++)
            #pragma unroll
            for (int r = 0; r < 4; r++) s[nt][r] = 0.f;

        #pragma unroll
        for (int kk = 0; kk < 8; kk++) {
            int kb = kk * 8 + kq;
            uint32_t b[8][2];
            #pragma unroll
            for (int nt = 0; nt < 8; nt++) {
                int n = nt * 8 + grp;
                b[nt][0] = Ks[n * ALD + kb];
                b[nt][1] = Ks[n * ALD + kb + 4];
            }
            #pragma unroll
            for (int nt = 0; nt < 8; nt++)
                mma_tf32(s[nt], qf[kk], b[nt]);
        }

        #pragma unroll
        for (int nt = 0; nt < 8; nt++) {
            float ka = k2s[nt * 8 + kq * 2];
            float kbv = k2s[nt * 8 + kq * 2 + 1];
            s[nt][0] -= ka; s[nt][1] -= kbv;
            s[nt][2] -= ka; s[nt][3] -= kbv;
        }

        float rm0 = -INFINITY, rm1 = -INFINITY;
        #pragma unroll
        for (int nt = 0; nt < 8; nt++) {
            rm0 = fmaxf(rm0, fmaxf(s[nt][0], s[nt][1]));
            rm1 = fmaxf(rm1, fmaxf(s[nt][2], s[nt][3]));
        }
        #pragma unroll
        for (int ofs = 1; ofs < 4; ofs <<= 1) {
            rm0 = fmaxf(rm0, __shfl_xor_sync(0xffffffffu, rm0, ofs));
            rm1 = fmaxf(rm1, __shfl_xor_sync(0xffffffffu, rm1, ofs));
        }
        float mn0 = fmaxf(m0, rm0), mn1 = fmaxf(m1, rm1);
        float al0 = __expf(m0 - mn0), al1 = __expf(m1 - mn1);
        float rs0 = 0.f, rs1 = 0.f;

        uint32_t* Ps = Qs;
        int prow = (wm + grp) * ALD + kq * 2;
        #pragma unroll
        for (int nt = 0; nt < 8; nt++) {
            float p0 = __expf(s[nt][0] - mn0);
            float p1 = __expf(s[nt][1] - mn0);
            float p2 = __expf(s[nt][2] - mn1);
            float p3 = __expf(s[nt][3] - mn1);
            rs0 += p0 + p1; rs1 += p2 + p3;
            Ps[prow + nt * 8]               = f2tf(p0);
            Ps[prow + nt * 8 + 1]           = f2tf(p1);
            Ps[prow + 8 * ALD + nt * 8]     = f2tf(p2);
            Ps[prow + 8 * ALD + nt * 8 + 1] = f2tf(p3);
        }
        #pragma unroll
        for (int ofs = 1; ofs < 4; ofs <<= 1) {
            rs0 += __shfl_xor_sync(0xffffffffu, rs0, ofs);
            rs1 += __shfl_xor_sync(0xffffffffu, rs1, ofs);
        }
        l0 = l0 * al0 + rs0; m0 = mn0;
        l1 = l1 * al1 + rs1; m1 = mn1;
        #pragma unroll
        for (int nt = 0; nt < 8; nt++) {
            o[nt][0] *= al0; o[nt][1] *= al0;
            o[nt][2] *= al1; o[nt][3] *= al1;
        }
        __syncwarp();

        #pragma unroll
        for (int kk = 0; kk < 8; kk++) {
            int kb = kk * 8 + kq, m = wm + grp;
            uint32_t a[4];
            a[0] = Ps[m * ALD + kb];
            a[1] = Ps[(m + 8) * ALD + kb];
            a[2] = Ps[m * ALD + kb + 4];
            a[3] = Ps[(m + 8) * ALD + kb + 4];
            uint32_t b[8][2];
            #pragma unroll
            for (int nt = 0; nt < 8; nt++) {
                int n = nt * 8 + grp;
                b[nt][0] = Vs[kb * ALD + n];
                b[nt][1] = Vs[(kb + 4) * ALD + n];
            }
            #pragma unroll
            for (int nt = 0; nt < 8; nt++)
                mma_tf32(o[nt], a, b[nt]);
        }
    }

    float inv0 = 1.0f / l0, inv1 = 1.0f / l1;
    int b_ = bh >> 4, h = bh & 15;
    int row0 = qb * 128 + wm + grp;
    #pragma unroll
    for (int nt = 0; nt < 8; nt++) {
        int col = h * HDc + nt * 8 + kq * 2;
        *(float2*)(out + ((size_t)(b_ * Lc + row0)) * Dc + col) =
            make_float2(f2tf_f(o[nt][0] * inv0), f2tf_f(o[nt][1] * inv0));
        *(float2*)(out + ((size_t)(b_ * Lc + row0 + 8)) * Dc + col) =
            make_float2(f2tf_f(o[nt][2] * inv1), f2tf_f(o[nt][3] * inv1));
    }
}

// -------------------------------- host ----------------------------------
static float* sym_ptr(const void* sym) {
    void* p = nullptr;
    cudaGetSymbolAddress(&p, sym);
    return (float*)p;
}

extern "C" void kernel_launch(void* const* d_in, const int* in_sizes, int n_in,
                              void* d_out, int out_size)
{
    const float* x   = (const float*)d_in[0];
    const float* wq  = (const float*)d_in[1];
    const float* bq  = (const float*)d_in[2];
    const float* wk  = (const float*)d_in[3];
    const float* bk  = (const float*)d_in[4];
    const float* wv  = (const float*)d_in[5];
    const float* bv  = (const float*)d_in[6];
    const float* wo  = (const float*)d_in[7];
    const float* bo  = (const float*)d_in[8];
    const float* g1  = (const float*)d_in[9];
    const float* b1  = (const float*)d_in[10];
    const float* g2  = (const float*)d_in[11];
    const float* b2  = (const float*)d_in[12];
    const float* w1  = (const float*)d_in[13];
    const float* bf1 = (const float*)d_in[14];
    const float* w2  = (const float*)d_in[15];
    const float* bf2 = (const float*)d_in[16];
    float* out = (float*)d_out;

    float* xn  = sym_ptr(g_xn);
    float* yq  = sym_ptr(g_yq);
    float* yk  = sym_ptr(g_yk);
    float* yv  = sym_ptr(g_yv);
    float* qd  = sym_ptr(g_q);
    float* kd  = sym_ptr(g_k);
    float* vd  = sym_ptr(g_v);
    float* k2d = sym_ptr(g_k2);
    float* att = sym_ptr(g_att);
    float* od  = sym_ptr(g_o);
    float* x2  = sym_ptr(g_x2);
    float* ffh = sym_ptr(g_ffh);
    float* f2  = sym_ptr(g_f2);
    float* twq = sym_ptr(g_twq);
    float* twk = sym_ptr(g_twk);
    float* twv = sym_ptr(g_twv);
    float* two = sym_ptr(g_two);
    float* tw1 = sym_ptr(g_tw1);
    float* tw2 = sym_ptr(g_tw2);

    cudaFuncSetAttribute(attn_mma_kernel, cudaFuncAttributeMaxDynamicSharedMemorySize, ATT_SMEM);

    // pre-round weights to tf32 once per launch (bit patterns valid mma input)
    int nDD = (Dc * Dc) / 4, nF = (DFc * Dc) / 4;
    round_tf32_kernel<<<(nDD + 255) / 256, 256>>>(wq, twq, nDD);
    round_tf32_kernel<<<(nDD + 255) / 256, 256>>>(wk, twk, nDD);
    round_tf32_kernel<<<(nDD + 255) / 256, 256>>>(wv, twv, nDD);
    round_tf32_kernel<<<(nDD + 255) / 256, 256>>>(wo, two, nDD);
    round_tf32_kernel<<<(nF + 255) / 256, 256>>>(w1, tw1, nF);
    round_tf32_kernel<<<(nF + 255) / 256, 256>>>(w2, tw2, nF);

    dim3 gProj(Dc / 128, Mc / 128);    // (8, 32)
    dim3 gFfn1(DFc / 128, Mc / 128);   // (32, 32)

    ln_kernel<<<Mc, 256>>>(x, g1, b1, xn);
    gemm_tf32<0><<<gProj, 256>>>(xn, twq, bq, yq, Mc, Dc, Dc);
    gemm_tf32<0><<<gProj, 256>>>(xn, twk, bk, yk, Mc, Dc, Dc);
    gemm_tf32<0><<<gProj, 256>>>(xn, twv, bv, yv, Mc, Dc, Dc);
    qkv_tr_kernel<<<Mc, 512>>>(yq, yk, yv, qd, kd, vd, k2d);

    attn_mma_kernel<<<dim3(Lc / 128, Bc * Hc), 256, ATT_SMEM>>>(qd, kd, vd, k2d, att);

    gemm_tf32<0><<<gProj, 256>>>(att, two, bo, od, Mc, Dc, Dc);
    resproj_kernel<<<Mc, 256>>>(x, od, x2);
    ln_kernel<<<Mc, 256>>>(x2, g2, b2, xn);
    gemm_tf32<1><<<gFfn1, 256>>>(xn, tw1, bf1, ffh, Mc, DFc, Dc);
    gemm_tf32<0><<<gProj, 256>>>(ffh, tw2, bf2, f2, Mc, Dc, DFc);
    resproj_kernel<<<Mc, 256>>>(x2, f2, out);
}

// round 8
// speedup vs baseline: 1.2989x; 1.0159x over previous
#include <cuda_runtime.h>
#include <math.h>
#include <stdint.h>

#define DEV_INLINE __device__ __forceinline__

// Problem dims
constexpr int Bc = 2;
constexpr int Lc = 2048;
constexpr int Dc = 1024;
constexpr int Hc = 16;
constexpr int HDc = 64;
constexpr int Mc = Bc * Lc;      // 4096 rows
constexpr int DFc = 4096;        // FFN hidden

// -------- scratch (static device globals; no allocation at runtime) --------
__device__ float g_xn [Mc * Dc];
__device__ float g_yq [Mc * Dc];
__device__ float g_yk [Mc * Dc];
__device__ float g_yv [Mc * Dc];
__device__ float g_q  [Mc * Dc];
__device__ float g_k  [Mc * Dc];
__device__ float g_v  [Mc * Dc];
__device__ float g_k2 [Bc * Hc * Lc];
__device__ float g_att[Mc * Dc];
__device__ float g_o  [Mc * Dc];
__device__ float g_x2 [Mc * Dc];
__device__ float g_ffh[(size_t)Mc * DFc];
__device__ float g_f2 [Mc * Dc];
// tf32-rounded weights
__device__ float g_twq[Dc * Dc];
__device__ float g_twk[Dc * Dc];
__device__ float g_twv[Dc * Dc];
__device__ float g_two[Dc * Dc];
__device__ float g_tw1[(size_t)DFc * Dc];
__device__ float g_tw2[(size_t)Dc * DFc];

DEV_INLINE float warp_sum(float v) {
    #pragma unroll
    for (int o = 16; o > 0; o >>= 1) v += __shfl_xor_sync(0xffffffffu, v, o);
    return v;
}

DEV_INLINE uint32_t f2tf(float x) {
    uint32_t r;
    asm("cvt.rna.tf32.f32 %0, %1;" : "=r"(r) : "f"(x));
    return r;
}
DEV_INLINE float f2tf_f(float x) { return __uint_as_float(f2tf(x)); }

DEV_INLINE void mma_tf32(float* c, const uint32_t* a, const uint32_t* b) {
    asm volatile(
        "mma.sync.aligned.m16n8k8.row.col.f32.tf32.tf32.f32 "
        "{%0,%1,%2,%3}, {%4,%5,%6,%7}, {%8,%9}, {%0,%1,%2,%3};\n"
        : "+f"(c[0]), "+f"(c[1]), "+f"(c[2]), "+f"(c[3])
        : "r"(a[0]), "r"(a[1]), "r"(a[2]), "r"(a[3]),
          "r"(b[0]), "r"(b[1]));
}

DEV_INLINE uint32_t smem_u32(const void* p) {
    uint32_t a;
    asm("{ .reg .u64 t; cvta.to.shared.u64 t, %1; cvt.u32.u64 %0, t; }"
        : "=r"(a) : "l"(p));
    return a;
}

DEV_INLINE void cp16(uint32_t dst, const void* src) {
    asm volatile("cp.async.cg.shared.global [%0], [%1], 16;" :: "r"(dst), "l"(src));
}
#define CP_COMMIT() asm volatile("cp.async.commit_group;" ::: "memory")
template<int N> DEV_INLINE void cp_wait() {
    asm volatile("cp.async.wait_group %0;" :: "n"(N) : "memory");
}

// ---------------- tf32 rounding pass (weights) ---------------------------
__global__ void round_tf32_kernel(const float* __restrict__ src,
                                  float* __restrict__ dst, int n4)
{
    int i = blockIdx.x * blockDim.x + threadIdx.x;
    if (i >= n4) return;
    float4 v = ((const float4*)src)[i];
    ((uint4*)dst)[i] = make_uint4(f2tf(v.x), f2tf(v.y), f2tf(v.z), f2tf(v.w));
}

// ---------------- LayerNorm (emits tf32-rounded output) ------------------
__global__ void ln_kernel(const float* __restrict__ x,
                          const float* __restrict__ g,
                          const float* __restrict__ b,
                          float* __restrict__ y)
{
    __shared__ float red[8];
    int row = blockIdx.x;
    int t = threadIdx.x;
    const float4* xr = (const float4*)(x + (size_t)row * Dc);
    float4 v = xr[t];

    float s = v.x + v.y + v.z + v.w;
    s = warp_sum(s);
    if ((t & 31) == 0) red[t >> 5] = s;
    __syncthreads();
    float tot = 0.f;
    #pragma unroll
    for (int i = 0; i < 8; i++) tot += red[i];
    float mean = tot * (1.0f / Dc);
    __syncthreads();

    float dx = v.x - mean, dy = v.y - mean, dz = v.z - mean, dw = v.w - mean;
    float s2 = dx*dx + dy*dy + dz*dz + dw*dw;
    s2 = warp_sum(s2);
    if ((t & 31) == 0) red[t >> 5] = s2;
    __syncthreads();
    float tot2 = 0.f;
    #pragma unroll
    for (int i = 0; i < 8; i++) tot2 += red[i];
    float rstd = rsqrtf(tot2 * (1.0f / Dc) + 1e-5f);

    float4 gg = ((const float4*)g)[t];
    float4 bb = ((const float4*)b)[t];
    float4 o;
    o.x = f2tf_f(dx * rstd * gg.x + bb.x);
    o.y = f2tf_f(dy * rstd * gg.y + bb.y);
    o.z = f2tf_f(dz * rstd * gg.z + bb.z);
    o.w = f2tf_f(dw * rstd * gg.w + bb.w);
    ((float4*)(y + (size_t)row * Dc))[t] = o;
}

// ---------------- residual + Poincare projection over full row ----------
__global__ void resproj_kernel(const float* __restrict__ x,
                               const float* __restrict__ add,
                               float* __restrict__ out)
{
    __shared__ float red[8];
    int row = blockIdx.x;
    int t = threadIdx.x;
    float4 a = ((const float4*)(x   + (size_t)row * Dc))[t];
    float4 c = ((const float4*)(add + (size_t)row * Dc))[t];
    float4 v = make_float4(a.x + c.x, a.y + c.y, a.z + c.z, a.w + c.w);

    float s = v.x*v.x + v.y*v.y + v.z*v.z + v.w*v.w;
    s = warp_sum(s);
    if ((t & 31) == 0) red[t >> 5] = s;
    __syncthreads();
    float tot = 0.f;
    #pragma unroll
    for (int i = 0; i < 8; i++) tot += red[i];
    float n = sqrtf(tot);
    const float maxn = 1.0f - 1e-5f;
    float sc = (n > maxn) ? (maxn / n) : 1.0f;

    v.x *= sc; v.y *= sc; v.z *= sc; v.w *= sc;
    ((float4*)(out + (size_t)row * Dc))[t] = v;
}

// ---------------- tf32 GEMM: R7 layout + 2-stage cp.async double buffer --
// C[M,N] = A[M,K] @ B[N,K]^T + bias, optional exact GELU (tf32-rounded out).
// Inputs pre-rounded to tf32. Identical smem layout (GLD=36), fragment
// gather, fill mapping, and epilogue as the proven R7 kernel. Only change:
// fills are cp.async issued TWO chunks ahead into a double buffer.
constexpr int GLD    = 36;
constexpr int MATW   = 128 * GLD;        // words per matrix (4608)
constexpr int STAGEW = 2 * MATW;         // A+B per stage
constexpr int G_SMEM = 2 * STAGEW * 4;   // 73728 bytes

template<int EPI>
__global__ __launch_bounds__(256, 2)
void gemm_tf32(const float* __restrict__ A, const float* __restrict__ B,
               const float* __restrict__ bias, float* __restrict__ C,
               int M, int N, int K)
{
    extern __shared__ uint32_t sh[];
    uint32_t shb = smem_u32(sh);

    int tid = threadIdx.x;
    int bm = blockIdx.y * 128, bn = blockIdx.x * 128;
    int lane = tid & 31, warp = tid >> 5;
    int wm = (warp & 3) * 32;
    int wn = (warp >> 2) * 64;
    int grp = lane >> 2, kq = lane & 3;

    float acc[2][8][4];
    #pragma unroll
    for (int mt = 0; mt < 2; mt++)
        #pragma unroll
        for (int nt = 0; nt < 8; nt++)
            #pragma unroll
            for (int r = 0; r < 4; r++) acc[mt][nt][r] = 0.f;

    int lrow = tid >> 3;            // 0..31 (+i*32)
    int lkc  = (tid & 7) * 4;       // 0,4,...,28
    const float* Ap = A + (size_t)(bm + lrow) * K + lkc;
    const float* Bp = B + (size_t)(bn + lrow) * K + lkc;

    const int nk = K / 32;

    auto issue = [&](int stage, int k0) {
        uint32_t base = shb + (uint32_t)stage * STAGEW * 4;
        #pragma unroll
        for (int i = 0; i < 4; i++) {
            int r = lrow + i * 32;
            cp16(base + (uint32_t)(r * GLD + lkc) * 4,
                 Ap + (size_t)i * 32 * K + k0);
            cp16(base + (uint32_t)(MATW + r * GLD + lkc) * 4,
                 Bp + (size_t)i * 32 * K + k0);
        }
        CP_COMMIT();
    };

    issue(0, 0);
    if (nk > 1) issue(1, 32);

    for (int it = 0; it < nk; it++) {
        if (it + 1 < nk) cp_wait<1>(); else cp_wait<0>();
        __syncthreads();

        const uint32_t* As = sh + (it & 1) * STAGEW;
        const uint32_t* Bs = As + MATW;

        #pragma unroll
        for (int kk = 0; kk < 4; kk++) {
            int kb = kk * 8 + kq;
            uint32_t a[2][4], b[8][2];
            #pragma unroll
            for (int mt = 0; mt < 2; mt++) {
                int m = wm + mt * 16 + grp;
                a[mt][0] = As[(m    ) * GLD + kb];
                a[mt][1] = As[(m + 8) * GLD + kb];
                a[mt][2] = As[(m    ) * GLD + kb + 4];
                a[mt][3] = As[(m + 8) * GLD + kb + 4];
            }
            #pragma unroll
            for (int nt = 0; nt < 8; nt++) {
                int n = wn + nt * 8 + grp;
                b[nt][0] = Bs[n * GLD + kb];
                b[nt][1] = Bs[n * GLD + kb + 4];
            }
            #pragma unroll
            for (int mt = 0; mt < 2; mt++)
                #pragma unroll
                for (int nt = 0; nt < 8; nt++)
                    mma_tf32(acc[mt][nt], a[mt], b[nt]);
        }
        __syncthreads();
        if (it + 2 < nk) issue(it & 1, (it + 2) * 32);
    }

    // epilogue (identical to R7)
    #pragma unroll
    for (int mt = 0; mt < 2; mt++) {
        int row0 = bm + wm + mt * 16 + grp;
        #pragma unroll
        for (int nt = 0; nt < 8; nt++) {
            int col = bn + wn + nt * 8 + kq * 2;
            float b0 = bias[col], b1 = bias[col + 1];
            float v0 = acc[mt][nt][0] + b0;
            float v1 = acc[mt][nt][1] + b1;
            float v2 = acc[mt][nt][2] + b0;
            float v3 = acc[mt][nt][3] + b1;
            if (EPI == 1) {
                v0 = f2tf_f(0.5f * v0 * (1.0f + erff(v0 * 0.70710678118654752f)));
                v1 = f2tf_f(0.5f * v1 * (1.0f + erff(v1 * 0.70710678118654752f)));
                v2 = f2tf_f(0.5f * v2 * (1.0f + erff(v2 * 0.70710678118654752f)));
                v3 = f2tf_f(0.5f * v3 * (1.0f + erff(v3 * 0.70710678118654752f)));
            }
            *(float2*)(C + (size_t)row0 * N + col)       = make_float2(v0, v1);
            *(float2*)(C + (size_t)(row0 + 8) * N + col) = make_float2(v2, v3);
        }
    }
}

// ---------------- head split + projection + prescaled q/k2 --------------
__global__ void qkv_tr_kernel(const float* __restrict__ yq,
                              const float* __restrict__ yk,
                              const float* __restrict__ yv,
                              float* __restrict__ q, float* __restrict__ k,
                              float* __restrict__ v, float* __restrict__ k2)
{
    int bl = blockIdx.x;
    int b = bl >> 11;
    int l = bl & 2047;
    int w = threadIdx.x >> 5;
    int lane = threadIdx.x & 31;
    const float maxn = 1.0f - 1e-5f;

    size_t src = (size_t)bl * Dc + w * HDc + lane * 2;
    size_t dst = ((size_t)(b * Hc + w) * Lc + l) * HDc + lane * 2;

    float2 qv = *(const float2*)(yq + src);
    float sq = warp_sum(qv.x*qv.x + qv.y*qv.y);
    float nq = sqrtf(sq);
    float scq = ((nq > maxn) ? (maxn / nq) : 1.0f) * 0.25f;
    *(float2*)(q + dst) = make_float2(qv.x * scq, qv.y * scq);

    float2 kv = *(const float2*)(yk + src);
    float sk = warp_sum(kv.x*kv.x + kv.y*kv.y);
    float nk = sqrtf(sk);
    float sck = (nk > maxn) ? (maxn / nk) : 1.0f;
    *(float2*)(k + dst) = make_float2(kv.x * sck, kv.y * sck);
    if (lane == 0) k2[(size_t)(b * Hc + w) * Lc + l] = sk * sck * sck * 0.125f;

    *(float2*)(v + dst) = *(const float2*)(yv + src);
}

// ---------------- flash attention, tf32 mma (R3-proven; rounds output) ---
constexpr int ALD = 68;
constexpr int ATT_SMEM = (128 * ALD + 64 * ALD + 64 * ALD) * 4 + 64 * 4;

__global__ __launch_bounds__(256, 2)
void attn_mma_kernel(const float* __restrict__ q, const float* __restrict__ k,
                     const float* __restrict__ v, const float* __restrict__ k2,
                     float* __restrict__ out)
{
    extern __shared__ uint32_t usm[];
    uint32_t* Qs = usm;
    uint32_t* Ks = Qs + 128 * ALD;
    uint32_t* Vs = Ks + 64 * ALD;
    float* k2s   = (float*)(Vs + 64 * ALD);

    int qb = blockIdx.x, bh = blockIdx.y;
    int tid = threadIdx.x, lane = tid & 31, warp = tid >> 5;
    int wm = warp * 16, grp = lane >> 2, kq = lane & 3;

    const float* qbase = q + ((size_t)bh * Lc + qb * 128) * HDc;
    #pragma unroll
    for (int it = 0; it < 8; it++) {
        int idx = tid + it * 256;
        int r = idx >> 4, c4 = (idx & 15) * 4;
        float4 t = *(const float4*)(qbase + r * HDc + c4);
        uint32_t* p = &Qs[r * ALD + c4];
        p[0] = f2tf(t.x); p[1] = f2tf(t.y); p[2] = f2tf(t.z); p[3] = f2tf(t.w);
    }
    __syncthreads();

    uint32_t qf[8][4];
    #pragma unroll
    for (int kk = 0; kk < 8; kk++) {
        int kb = kk * 8 + kq, m = wm + grp;
        qf[kk][0] = Qs[m * ALD + kb];
        qf[kk][1] = Qs[(m + 8) * ALD + kb];
        qf[kk][2] = Qs[m * ALD + kb + 4];
        qf[kk][3] = Qs[(m + 8) * ALD + kb + 4];
    }

    float o[8][4];
    #pragma unroll
    for (int nt = 0; nt < 8; nt++)
        #pragma unroll
        for (int r = 0; r < 4; r++) o[nt][r] = 0.f;
    float m0 = -INFINITY, m1 = -INFINITY, l0 = 0.f, l1 = 0.f;

    for (int jb = 0; jb < Lc / 64; jb++) {
        __syncthreads();
        const float* kb_ = k + ((size_t)bh * Lc + jb * 64) * HDc;
        const float* vb_ = v + ((size_t)bh * Lc + jb * 64) * HDc;
        #pragma unroll
        for (int it = 0; it < 4; it++) {
            int idx = tid + it * 256;
            int r = idx >> 4, c4 = (idx & 15) * 4;
            float4 a = *(const float4*)(kb_ + r * HDc + c4);
            uint32_t* kp = &Ks[r * ALD + c4];
            kp[0] = f2tf(a.x); kp[1] = f2tf(a.y); kp[2] = f2tf(a.z); kp[3] = f2tf(a.w);
            float4 bv = *(const float4*)(vb_ + r * HDc + c4);
            uint32_t* vp = &Vs[r * ALD + c4];
            vp[0] = f2tf(bv.x); vp[1] = f2tf(bv.y); vp[2] = f2tf(bv.z); vp[3] = f2tf(bv.w);
        }
        if (tid < 64) k2s[tid] = k2[(size_t)bh * Lc + jb * 64 + tid];
        __syncthreads();

        float s[8][4];
        #pragma unroll
        for (int nt = 0; nt < 8; nt++)
            #pragma unroll
            for (int r = 0; r < 4; r++) s[nt][r] = 0.f;

        #pragma unroll
        for (int kk = 0; kk < 8; kk++) {
            int kb = kk * 8 + kq;
            uint32_t b[8][2];
            #pragma unroll
            for (int nt = 0; nt < 8; nt++) {
                int n = nt * 8 + grp;
                b[nt][0] = Ks[n * ALD + kb];
                b[nt][1] = Ks[n * ALD + kb + 4];
            }
            #pragma unroll
            for (int nt = 0; nt < 8; nt++)
                mma_tf32(s[nt], qf[kk], b[nt]);
        }

        #pragma unroll
        for (int nt = 0; nt < 8; nt++) {
            float ka = k2s[nt * 8 + kq * 2];
            float kbv = k2s[nt * 8 + kq * 2 + 1];
            s[nt][0] -= ka; s[nt][1] -= kbv;
            s[nt][2] -= ka; s[nt][3] -= kbv;
        }

        float rm0 = -INFINITY, rm1 = -INFINITY;
        #pragma unroll
        for (int nt = 0; nt < 8; nt++) {
            rm0 = fmaxf(rm0, fmaxf(s[nt][0], s[nt][1]));
            rm1 = fmaxf(rm1, fmaxf(s[nt][2], s[nt][3]));
        }
        #pragma unroll
        for (int ofs = 1; ofs < 4; ofs <<= 1) {
            rm0 = fmaxf(rm0, __shfl_xor_sync(0xffffffffu, rm0, ofs));
            rm1 = fmaxf(rm1, __shfl_xor_sync(0xffffffffu, rm1, ofs));
        }
        float mn0 = fmaxf(m0, rm0), mn1 = fmaxf(m1, rm1);
        float al0 = __expf(m0 - mn0), al1 = __expf(m1 - mn1);
        float rs0 = 0.f, rs1 = 0.f;

        uint32_t* Ps = Qs;
        int prow = (wm + grp) * ALD + kq * 2;
        #pragma unroll
        for (int nt = 0; nt < 8; nt++) {
            float p0 = __expf(s[nt][0] - mn0);
            float p1 = __expf(s[nt][1] - mn0);
            float p2 = __expf(s[nt][2] - mn1);
            float p3 = __expf(s[nt][3] - mn1);
            rs0 += p0 + p1; rs1 += p2 + p3;
            Ps[prow + nt * 8]               = f2tf(p0);
            Ps[prow + nt * 8 + 1]           = f2tf(p1);
            Ps[prow + 8 * ALD + nt * 8]     = f2tf(p2);
            Ps[prow + 8 * ALD + nt * 8 + 1] = f2tf(p3);
        }
        #pragma unroll
        for (int ofs = 1; ofs < 4; ofs <<= 1) {
            rs0 += __shfl_xor_sync(0xffffffffu, rs0, ofs);
            rs1 += __shfl_xor_sync(0xffffffffu, rs1, ofs);
        }
        l0 = l0 * al0 + rs0; m0 = mn0;
        l1 = l1 * al1 + rs1; m1 = mn1;
        #pragma unroll
        for (int nt = 0; nt < 8; nt++) {
            o[nt][0] *= al0; o[nt][1] *= al0;
            o[nt][2] *= al1; o[nt][3] *= al1;
        }
        __syncwarp();

        #pragma unroll
        for (int kk = 0; kk < 8; kk++) {
            int kb = kk * 8 + kq, m = wm + grp;
            uint32_t a[4];
            a[0] = Ps[m * ALD + kb];
            a[1] = Ps[(m + 8) * ALD + kb];
            a[2] = Ps[m * ALD + kb + 4];
            a[3] = Ps[(m + 8) * ALD + kb + 4];
            uint32_t b[8][2];
            #pragma unroll
            for (int nt = 0; nt < 8; nt++) {
                int n = nt * 8 + grp;
                b[nt][0] = Vs[kb * ALD + n];
                b[nt][1] = Vs[(kb + 4) * ALD + n];
            }
            #pragma unroll
            for (int nt = 0; nt < 8; nt++)
                mma_tf32(o[nt], a, b[nt]);
        }
    }

    float inv0 = 1.0f / l0, inv1 = 1.0f / l1;
    int b_ = bh >> 4, h = bh & 15;
    int row0 = qb * 128 + wm + grp;
    #pragma unroll
    for (int nt = 0; nt < 8; nt++) {
        int col = h * HDc + nt * 8 + kq * 2;
        *(float2*)(out + ((size_t)(b_ * Lc + row0)) * Dc + col) =
            make_float2(f2tf_f(o[nt][0] * inv0), f2tf_f(o[nt][1] * inv0));
        *(float2*)(out + ((size_t)(b_ * Lc + row0 + 8)) * Dc + col) =
            make_float2(f2tf_f(o[nt][2] * inv1), f2tf_f(o[nt][3] * inv1));
    }
}

// -------------------------------- host ----------------------------------
static float* sym_ptr(const void* sym) {
    void* p = nullptr;
    cudaGetSymbolAddress(&p, sym);
    return (float*)p;
}

extern "C" void kernel_launch(void* const* d_in, const int* in_sizes, int n_in,
                              void* d_out, int out_size)
{
    const float* x   = (const float*)d_in[0];
    const float* wq  = (const float*)d_in[1];
    const float* bq  = (const float*)d_in[2];
    const float* wk  = (const float*)d_in[3];
    const float* bk  = (const float*)d_in[4];
    const float* wv  = (const float*)d_in[5];
    const float* bv  = (const float*)d_in[6];
    const float* wo  = (const float*)d_in[7];
    const float* bo  = (const float*)d_in[8];
    const float* g1  = (const float*)d_in[9];
    const float* b1  = (const float*)d_in[10];
    const float* g2  = (const float*)d_in[11];
    const float* b2  = (const float*)d_in[12];
    const float* w1  = (const float*)d_in[13];
    const float* bf1 = (const float*)d_in[14];
    const float* w2  = (const float*)d_in[15];
    const float* bf2 = (const float*)d_in[16];
    float* out = (float*)d_out;

    float* xn  = sym_ptr(g_xn);
    float* yq  = sym_ptr(g_yq);
    float* yk  = sym_ptr(g_yk);
    float* yv  = sym_ptr(g_yv);
    float* qd  = sym_ptr(g_q);
    float* kd  = sym_ptr(g_k);
    float* vd  = sym_ptr(g_v);
    float* k2d = sym_ptr(g_k2);
    float* att = sym_ptr(g_att);
    float* od  = sym_ptr(g_o);
    float* x2  = sym_ptr(g_x2);
    float* ffh = sym_ptr(g_ffh);
    float* f2  = sym_ptr(g_f2);
    float* twq = sym_ptr(g_twq);
    float* twk = sym_ptr(g_twk);
    float* twv = sym_ptr(g_twv);
    float* two = sym_ptr(g_two);
    float* tw1 = sym_ptr(g_tw1);
    float* tw2 = sym_ptr(g_tw2);

    cudaFuncSetAttribute(gemm_tf32<0>, cudaFuncAttributeMaxDynamicSharedMemorySize, G_SMEM);
    cudaFuncSetAttribute(gemm_tf32<1>, cudaFuncAttributeMaxDynamicSharedMemorySize, G_SMEM);
    cudaFuncSetAttribute(attn_mma_kernel, cudaFuncAttributeMaxDynamicSharedMemorySize, ATT_SMEM);

    // pre-round weights to tf32 once per launch (bit patterns valid mma input)
    int nDD = (Dc * Dc) / 4, nF = (DFc * Dc) / 4;
    round_tf32_kernel<<<(nDD + 255) / 256, 256>>>(wq, twq, nDD);
    round_tf32_kernel<<<(nDD + 255) / 256, 256>>>(wk, twk, nDD);
    round_tf32_kernel<<<(nDD + 255) / 256, 256>>>(wv, twv, nDD);
    round_tf32_kernel<<<(nDD + 255) / 256, 256>>>(wo, two, nDD);
    round_tf32_kernel<<<(nF + 255) / 256, 256>>>(w1, tw1, nF);
    round_tf32_kernel<<<(nF + 255) / 256, 256>>>(w2, tw2, nF);

    dim3 gProj(Dc / 128, Mc / 128);    // (8, 32)
    dim3 gFfn1(DFc / 128, Mc / 128);   // (32, 32)

    ln_kernel<<<Mc, 256>>>(x, g1, b1, xn);
    gemm_tf32<0><<<gProj, 256, G_SMEM>>>(xn, twq, bq, yq, Mc, Dc, Dc);
    gemm_tf32<0><<<gProj, 256, G_SMEM>>>(xn, twk, bk, yk, Mc, Dc, Dc);
    gemm_tf32<0><<<gProj, 256, G_SMEM>>>(xn, twv, bv, yv, Mc, Dc, Dc);
    qkv_tr_kernel<<<Mc, 512>>>(yq, yk, yv, qd, kd, vd, k2d);

    attn_mma_kernel<<<dim3(Lc / 128, Bc * Hc), 256, ATT_SMEM>>>(qd, kd, vd, k2d, att);

    gemm_tf32<0><<<gProj, 256, G_SMEM>>>(att, two, bo, od, Mc, Dc, Dc);
    resproj_kernel<<<Mc, 256>>>(x, od, x2);
    ln_kernel<<<Mc, 256>>>(x2, g2, b2, xn);
    gemm_tf32<1><<<gFfn1, 256, G_SMEM>>>(xn, tw1, bf1, ffh, Mc, DFc, Dc);
    gemm_tf32<0><<<gProj, 256, G_SMEM>>>(ffh, tw2, bf2, f2, Mc, Dc, DFc);
    resproj_kernel<<<Mc, 256>>>(x2, f2, out);
}